// round 13
// baseline (speedup 1.0000x reference)
#include <cuda_runtime.h>
#include <cuda_fp16.h>
#include <stdint.h>
#include <math.h>

#define B_  4
#define T_  2048
#define D_  1024
#define H_  8
#define DK_ 128
#define P_  (2*T_-1)
#define BT_ (B_*T_)
#define BDW 2304            // bd band row width (f16 elems)

typedef __half f16;

// ---------------- scratch (device globals: allocation-free) ----------------
static __device__ __align__(16) f16 g_xh [(size_t)BT_ * D_];
static __device__ __align__(16) f16 g_peh[(size_t)P_ * D_];
static __device__ __align__(16) f16 g_wqh[(size_t)D_ * D_], g_wql[(size_t)D_ * D_];
static __device__ __align__(16) f16 g_wkh[(size_t)D_ * D_], g_wkl[(size_t)D_ * D_];
static __device__ __align__(16) f16 g_wvh[(size_t)D_ * D_], g_wvl[(size_t)D_ * D_];
static __device__ __align__(16) f16 g_woh[(size_t)D_ * D_], g_wol[(size_t)D_ * D_];
static __device__ __align__(16) f16 g_wph[(size_t)D_ * D_], g_wpl[(size_t)D_ * D_];
static __device__ __align__(16) f16 g_quh[(size_t)BT_ * D_];
static __device__ __align__(16) f16 g_qvh[(size_t)BT_ * D_];
static __device__ __align__(16) f16 g_kh [(size_t)BT_ * D_], g_kl [(size_t)BT_ * D_];
static __device__ __align__(16) f16 g_ph [(size_t)P_ * D_],  g_pl [(size_t)P_ * D_];
static __device__ __align__(16) float g_v [(size_t)BT_ * D_];
static __device__ __align__(16) f16 g_vth[(size_t)B_ * H_ * DK_ * T_];
static __device__ __align__(16) f16 g_bdh[(size_t)B_ * H_ * T_ * BDW];   // rel-pos band, fp16
static __device__ __align__(16) f16 g_aoh[(size_t)BT_ * D_];

// ============================ helpers ============================
__device__ __forceinline__ uint32_t smem_u32(const void* p) {
    uint32_t a;
    asm("{ .reg .u64 t; cvta.to.shared.u64 t, %1; cvt.u32.u64 %0, t; }" : "=r"(a) : "l"(p));
    return a;
}

__device__ __forceinline__ void split2h(float a, float b, __half2& h, __half2& l) {
    f16 ha = __float2half_rn(a), hb = __float2half_rn(b);
    h = __halves2half2(ha, hb);
    l = __halves2half2(__float2half_rn(a - __half2float(ha)),
                       __float2half_rn(b - __half2float(hb)));
}

__device__ __forceinline__ uint32_t pkh2(float a, float b) {
    __half2 h = __halves2half2(__float2half_rn(a), __float2half_rn(b));
    return *(uint32_t*)&h;
}

#define LDSM4(r0, r1, r2, r3, addr) \
    asm volatile("ldmatrix.sync.aligned.m8n8.x4.shared.b16 {%0,%1,%2,%3}, [%4];" \
        : "=r"(r0), "=r"(r1), "=r"(r2), "=r"(r3) : "r"(addr))

#define MMA16816(c, a, b0, b1) \
    asm volatile("mma.sync.aligned.m16n8k16.row.col.f32.f16.f16.f32 " \
        "{%0,%1,%2,%3}, {%4,%5,%6,%7}, {%8,%9}, {%0,%1,%2,%3};" \
        : "+f"((c)[0]), "+f"((c)[1]), "+f"((c)[2]), "+f"((c)[3]) \
        : "r"((a)[0]), "r"((a)[1]), "r"((a)[2]), "r"((a)[3]), "r"(b0), "r"(b1))

#define CP16(dst, src, sz) \
    asm volatile("cp.async.cg.shared.global [%0], [%1], 16, %2;" \
        :: "r"(dst), "l"(src), "r"(sz))
#define CP_COMMIT() asm volatile("cp.async.commit_group;")
#define CP_WAIT(n)  asm volatile("cp.async.wait_group %0;" :: "n"(n))

// ---------------- fused prologue: y=0 cvt x, y=1 cvt pe, y=2..6 split weights ----------------
__global__ void __launch_bounds__(256) prep(
        const float* __restrict__ x, const float* __restrict__ pe,
        const float* __restrict__ Wq, const float* __restrict__ Wk,
        const float* __restrict__ Wv, const float* __restrict__ Wo,
        const float* __restrict__ Wp,
        f16* __restrict__ xh, f16* __restrict__ peh,
        f16* wqh, f16* wql, f16* wkh, f16* wkl, f16* wvh, f16* wvl,
        f16* woh, f16* wol, f16* wph, f16* wpl) {
    int y = blockIdx.y;
    int i = (blockIdx.x * 256 + threadIdx.x) * 4;
    if (y <= 1) {
        const float* s = (y == 0) ? x : pe;
        f16* h = (y == 0) ? xh : peh;
        int n = (y == 0) ? BT_ * D_ : P_ * D_;
        if (i >= n) return;
        float4 v = *(const float4*)&s[i];
        *(__half2*)&h[i]     = __halves2half2(__float2half_rn(v.x), __float2half_rn(v.y));
        *(__half2*)&h[i + 2] = __halves2half2(__float2half_rn(v.z), __float2half_rn(v.w));
    } else {
        if (i >= D_ * D_) return;
        const float* s = (y == 2) ? Wq : (y == 3) ? Wk : (y == 4) ? Wv : (y == 5) ? Wo : Wp;
        f16* h = (y == 2) ? wqh : (y == 3) ? wkh : (y == 4) ? wvh : (y == 5) ? woh : wph;
        f16* l = (y == 2) ? wql : (y == 3) ? wkl : (y == 4) ? wvl : (y == 5) ? wol : wpl;
        float4 v = *(const float4*)&s[i];
        __half2 h0, l0, h1, l1;
        split2h(v.x, v.y, h0, l0);
        split2h(v.z, v.w, h1, l1);
        *(__half2*)&h[i]     = h0;
        *(__half2*)&h[i + 2] = h1;
        *(__half2*)&l[i]     = l0;
        *(__half2*)&l[i + 2] = l1;
    }
}

// ======== warp-MMA NT GEMM: 128x128 tile, A fp16, B fp16 hi/lo, 2 passes ========
#define KC    32
#define LDST  40
#define ARRB  (128 * LDST * 2)
#define SS    (3 * ARRB)
#define NSTG  3
#define SMEMSZ (NSTG * SS)
#define OFF_AH 0
#define OFF_BH ARRB
#define OFF_BL (2 * ARRB)

__device__ __forceinline__ void mm2_body(
        const f16* __restrict__ Ah, int lda, int m0, int Mrows,
        const f16* __restrict__ Bh, const f16* __restrict__ Bl, int ldb, int n0, int Nrows,
        int K, float acc[2][8][4]) {
    extern __shared__ char dsm[];
    uint32_t sb = smem_u32(dsm);
    int tid = threadIdx.x, lane = tid & 31, wid = tid >> 5;
    int wm = (wid & 3) * 32, wn = (wid >> 2) * 64;
    int lr = lane & 15, lc8 = (lane >> 4) << 3;

    #pragma unroll
    for (int mt = 0; mt < 2; mt++)
        #pragma unroll
        for (int nt = 0; nt < 8; nt++)
            #pragma unroll
            for (int e = 0; e < 4; e++) acc[mt][nt][e] = 0.f;

    auto stage_fill = [&](int st, int kc) {
        uint32_t base = sb + st * SS;
        #pragma unroll
        for (int i = 0; i < 6; i++) {
            int sidx = tid + (i << 8);
            int arr = sidx >> 9;
            int rem = sidx & 511;
            int row = rem >> 2, seg = rem & 3;
            uint32_t doff = arr * ARRB + row * (LDST * 2) + seg * 16;
            const char* src;
            int sz;
            if (arr == 0) {
                int r = m0 + row;
                src = (const char*)(Ah + (size_t)r * lda + kc) + seg * 16;
                sz = (r < Mrows) ? 16 : 0;
            } else if (arr == 1) {
                int r = n0 + row;
                src = (const char*)(Bh + (size_t)r * ldb + kc) + seg * 16;
                sz = (r < Nrows) ? 16 : 0;
            } else {
                int r = n0 + row;
                src = (const char*)(Bl + (size_t)r * ldb + kc) + seg * 16;
                sz = (r < Nrows) ? 16 : 0;
            }
            CP16(base + doff, src, sz);
        }
    };

    const int NC = K / KC;
    stage_fill(0, 0);
    CP_COMMIT();
    if (NC > 1) { stage_fill(1, KC); CP_COMMIT(); }

    for (int c = 0; c < NC; c++) {
        if (c < NC - 1) CP_WAIT(1); else CP_WAIT(0);
        __syncthreads();

        uint32_t abase = sb + (c % NSTG) * SS;
        #pragma unroll
        for (int kk = 0; kk < KC; kk += 16) {
            uint32_t ah[2][4];
            #pragma unroll
            for (int mt = 0; mt < 2; mt++) {
                uint32_t r = abase + OFF_AH + (wm + mt * 16 + lr) * (LDST * 2) + (kk + lc8) * 2;
                LDSM4(ah[mt][0], ah[mt][1], ah[mt][2], ah[mt][3], r);
            }
            #pragma unroll
            for (int g = 0; g < 4; g++) {
                uint32_t bh0, bh1, bh2, bh3, bl0, bl1, bl2, bl3;
                uint32_t r = abase + OFF_BH + (wn + g * 16 + lr) * (LDST * 2) + (kk + lc8) * 2;
                LDSM4(bh0, bh1, bh2, bh3, r);
                r = abase + OFF_BL + (wn + g * 16 + lr) * (LDST * 2) + (kk + lc8) * 2;
                LDSM4(bl0, bl1, bl2, bl3, r);
                #pragma unroll
                for (int mt = 0; mt < 2; mt++) {
                    MMA16816(acc[mt][2 * g],     ah[mt], bh0, bh2);
                    MMA16816(acc[mt][2 * g + 1], ah[mt], bh1, bh3);
                    MMA16816(acc[mt][2 * g],     ah[mt], bl0, bl2);
                    MMA16816(acc[mt][2 * g + 1], ah[mt], bl1, bl3);
                }
            }
        }
        if (c + 2 < NC) { stage_fill((c + 2) % NSTG, (c + 2) * KC); CP_COMMIT(); }
    }
}

#define ACC_PAIRS(...) do {                                                   \
    int lane = threadIdx.x & 31, wid = threadIdx.x >> 5;                      \
    int wm = (wid & 3) * 32, wn = (wid >> 2) * 64;                            \
    int g = lane >> 2, tg = lane & 3;                                         \
    _Pragma("unroll") for (int mt = 0; mt < 2; mt++)                          \
    _Pragma("unroll") for (int hf = 0; hf < 2; hf++) {                        \
        int rl = wm + mt * 16 + g + hf * 8;                                   \
        _Pragma("unroll") for (int nt = 0; nt < 8; nt++) {                    \
            int cl = wn + nt * 8 + tg * 2;                                    \
            float v0 = acc[mt][nt][hf * 2], v1 = acc[mt][nt][hf * 2 + 1];     \
            { __VA_ARGS__ }                                                   \
        }                                                                     \
    }                                                                         \
} while (0)

// ---------------- projections: z=0 q(+biases), 1 k, 2 v, 3 p ----------------
__global__ void __launch_bounds__(256, 2) mm_proj(
        const f16* xh, const f16* peh,
        const f16* wqh, const f16* wql, const f16* wkh, const f16* wkl,
        const f16* wvh, const f16* wvl, const f16* wph, const f16* wpl,
        const float* bu, const float* bv,
        f16* quh, f16* qvh, f16* kh, f16* kl, float* v, f16* ph, f16* pl) {
    int z = blockIdx.z;
    const f16* Ah = (z == 3) ? peh : xh;
    const f16* Bh = (z == 0) ? wqh : (z == 1) ? wkh : (z == 2) ? wvh : wph;
    const f16* Bl = (z == 0) ? wql : (z == 1) ? wkl : (z == 2) ? wvl : wpl;
    int M = (z == 3) ? P_ : BT_;
    int m0 = blockIdx.y * 128;
    if (m0 >= M) return;
    int n0 = blockIdx.x * 128;
    float acc[2][8][4];
    mm2_body(Ah, D_, m0, M, Bh, Bl, D_, n0, D_, D_, acc);

    if (z == 0) {
        ACC_PAIRS(
            int r = m0 + rl, c = n0 + cl;
            size_t idx = (size_t)r * D_ + c;
            *(__half2*)&quh[idx] = __halves2half2(
                __float2half_rn(v0 + __ldg(&bu[c])), __float2half_rn(v1 + __ldg(&bu[c + 1])));
            *(__half2*)&qvh[idx] = __halves2half2(
                __float2half_rn(v0 + __ldg(&bv[c])), __float2half_rn(v1 + __ldg(&bv[c + 1])));
        );
    } else if (z == 1) {
        ACC_PAIRS(
            size_t idx = (size_t)(m0 + rl) * D_ + n0 + cl;
            __half2 h, l;
            split2h(v0, v1, h, l);
            *(__half2*)&kh[idx] = h; *(__half2*)&kl[idx] = l;
        );
    } else if (z == 2) {
        ACC_PAIRS(
            *(float2*)&v[(size_t)(m0 + rl) * D_ + n0 + cl] = make_float2(v0, v1);
        );
    } else {
        ACC_PAIRS(
            int r = m0 + rl;
            if (r < P_) {
                size_t idx = (size_t)r * D_ + n0 + cl;
                __half2 h, l;
                split2h(v0, v1, h, l);
                *(__half2*)&ph[idx] = h; *(__half2*)&pl[idx] = l;
            }
        );
    }
}

// ---- scores BD diag GEMM, fp16 band, pure write: bd[q][k+128] = (q+v)·p[k-q+T-1]
__global__ void __launch_bounds__(256, 2) scores_bd(const f16* qvh,
                                                    const f16* ph, const f16* pl,
                                                    f16* __restrict__ bd) {
    int bh = blockIdx.z, b = bh >> 3, h = bh & 7;
    int qi = blockIdx.y;
    int j0 = (15 - qi + (int)blockIdx.x) * 128;
    size_t abase = (size_t)b * T_ * D_ + h * DK_;
    int m0 = qi * 128;
    float acc[2][8][4];
    mm2_body(qvh + abase, D_, m0, T_, ph + h * DK_, pl + h * DK_, D_, j0, P_, DK_, acc);
    f16* bdo = bd + (size_t)bh * T_ * BDW;
    ACC_PAIRS(
        int q = m0 + rl;
        int c = j0 + cl + q - 1919;           // c = k + 128, in [1, 2303]
        f16* row = &bdo[(size_t)q * BDW];
        row[c] = __float2half_rn(v0); row[c + 1] = __float2half_rn(v1);
    );
}

// ---------------- v transpose: vt[bh][dk][t], fp16 ----------------
__global__ void __launch_bounds__(256) vtrans(const float* __restrict__ v,
                                              f16* __restrict__ vth) {
    __shared__ float tile[32][33];
    int bh = blockIdx.z, b = bh >> 3, h = bh & 7;
    int t0 = blockIdx.x * 32, d0 = blockIdx.y * 32;
    int tx = threadIdx.x & 31, ty = threadIdx.x >> 5;
    #pragma unroll
    for (int i = 0; i < 4; ++i) {
        int t = t0 + ty + i * 8;
        tile[ty + i * 8][tx] = v[(size_t)(b * T_ + t) * D_ + h * DK_ + d0 + tx];
    }
    __syncthreads();
    #pragma unroll
    for (int i = 0; i < 4; ++i) {
        int dk = d0 + ty + i * 8;
        vth[((size_t)bh * DK_ + dk) * T_ + t0 + tx] = __float2half_rn(tile[tx][ty + i * 8]);
    }
}

// ======== flash attention: QK(2-pass) + fp16 bd + online softmax + PV(1-pass) ========
// block = 256 thr (8 warps x 16 q-rows), q-tile 128, streams 16 k-tiles.
#define LDSTF 136
#define FARR  (128 * LDSTF * 2)      // 34816
#define FSLOT (2 * FARR)             // 69632 (hi + lo; V uses hi only)
#define FSMEM (3 * FSLOT)            // 208896

__global__ void __launch_bounds__(256, 1) flash_kernel(
        const f16* __restrict__ quh,
        const f16* __restrict__ kh, const f16* __restrict__ kl,
        const f16* __restrict__ vth,
        const f16* __restrict__ bd, f16* __restrict__ aoh) {
    extern __shared__ char dsm[];
    uint32_t sb = smem_u32(dsm);
    int qt = blockIdx.x, bh = blockIdx.y, b = bh >> 3, h = bh & 7;
    int q0 = qt * 128;
    int tid = threadIdx.x, lane = tid & 31, wid = tid >> 5;
    int wm = wid * 16;
    int g = lane >> 2, tg = lane & 3;
    int lr = lane & 15, lc8 = (lane >> 4) << 3;

    const f16* qbase = quh + ((size_t)(b * T_ + q0 + wm)) * D_ + h * DK_;
    uint32_t quf[8][4];
    #pragma unroll
    for (int kk = 0; kk < 8; kk++) {
        quf[kk][0] = *(const uint32_t*)(qbase + (size_t)g * D_ + kk * 16 + 2 * tg);
        quf[kk][1] = *(const uint32_t*)(qbase + (size_t)(g + 8) * D_ + kk * 16 + 2 * tg);
        quf[kk][2] = *(const uint32_t*)(qbase + (size_t)g * D_ + kk * 16 + 2 * tg + 8);
        quf[kk][3] = *(const uint32_t*)(qbase + (size_t)(g + 8) * D_ + kk * 16 + 2 * tg + 8);
    }

    float O[16][4];
    #pragma unroll
    for (int nt = 0; nt < 16; nt++)
        #pragma unroll
        for (int e = 0; e < 4; e++) O[nt][e] = 0.f;
    float mrow0 = -1e30f, mrow1 = -1e30f, lrow0 = 0.f, lrow1 = 0.f;

    auto stage = [&](int slot, int kt, int kind) {
        uint32_t base = sb + slot * FSLOT;
        if (kind == 0) {
            const f16* sh = kh + ((size_t)(b * T_ + kt * 128)) * D_ + h * DK_;
            const f16* sl = kl + ((size_t)(b * T_ + kt * 128)) * D_ + h * DK_;
            #pragma unroll
            for (int i = 0; i < 8; i++) {
                int idx = tid + (i << 8);
                int row = idx >> 4, seg = idx & 15;
                uint32_t doff = row * (LDSTF * 2) + seg * 16;
                CP16(base + doff,        (const char*)(sh + (size_t)row * D_) + seg * 16, 16);
                CP16(base + FARR + doff, (const char*)(sl + (size_t)row * D_) + seg * 16, 16);
            }
        } else {
            const f16* sh = vth + (size_t)bh * DK_ * T_ + kt * 128;
            #pragma unroll
            for (int i = 0; i < 8; i++) {
                int idx = tid + (i << 8);
                int row = idx >> 4, seg = idx & 15;
                uint32_t doff = row * (LDSTF * 2) + seg * 16;
                CP16(base + doff, (const char*)(sh + (size_t)row * T_) + seg * 16, 16);
            }
        }
    };

    const float scale = 0.08838834764831845f;
    const f16* bdr0 = bd + ((size_t)bh * T_ + q0 + wm + g) * BDW + 2 * tg + 128;
    const f16* bdr1 = bdr0 + (size_t)8 * BDW;

    stage(0, 0, 0); CP_COMMIT();
    stage(1, 0, 1); CP_COMMIT();

    for (int kt = 0; kt < 16; kt++) {
        int sK = (2 * kt) % 3, sV = (2 * kt + 1) % 3;
        if (kt < 15) { stage((2 * kt + 2) % 3, kt + 1, 0); CP_COMMIT(); CP_WAIT(2); }
        else CP_WAIT(1);
        __syncthreads();

        // ---- QK: S = qu · K^T (hi + lo passes) ----
        float S[16][4];
        #pragma unroll
        for (int nt = 0; nt < 16; nt++)
            #pragma unroll
            for (int e = 0; e < 4; e++) S[nt][e] = 0.f;
        uint32_t kb = sb + sK * FSLOT;
        #pragma unroll
        for (int kk = 0; kk < 8; kk++) {
            #pragma unroll
            for (int gg = 0; gg < 8; gg++) {
                uint32_t b0, b1, b2, b3, c0, c1, c2, c3;
                uint32_t r = kb + (gg * 16 + lr) * (LDSTF * 2) + (kk * 16 + lc8) * 2;
                LDSM4(b0, b1, b2, b3, r);
                LDSM4(c0, c1, c2, c3, r + FARR);
                MMA16816(S[2 * gg],     quf[kk], b0, b2);
                MMA16816(S[2 * gg + 1], quf[kk], b1, b3);
                MMA16816(S[2 * gg],     quf[kk], c0, c2);
                MMA16816(S[2 * gg + 1], quf[kk], c1, c3);
            }
        }

        // ---- add rel-pos band + scale, row max ----
        float mx0 = -1e30f, mx1 = -1e30f;
        #pragma unroll
        for (int nt = 0; nt < 16; nt++) {
            float2 d0 = __half22float2(*(const __half2*)(bdr0 + kt * 128 + nt * 8));
            float2 d1 = __half22float2(*(const __half2*)(bdr1 + kt * 128 + nt * 8));
            S[nt][0] = (S[nt][0] + d0.x) * scale;
            S[nt][1] = (S[nt][1] + d0.y) * scale;
            S[nt][2] = (S[nt][2] + d1.x) * scale;
            S[nt][3] = (S[nt][3] + d1.y) * scale;
            mx0 = fmaxf(mx0, fmaxf(S[nt][0], S[nt][1]));
            mx1 = fmaxf(mx1, fmaxf(S[nt][2], S[nt][3]));
        }
        mx0 = fmaxf(mx0, __shfl_xor_sync(0xffffffffu, mx0, 1));
        mx0 = fmaxf(mx0, __shfl_xor_sync(0xffffffffu, mx0, 2));
        mx1 = fmaxf(mx1, __shfl_xor_sync(0xffffffffu, mx1, 1));
        mx1 = fmaxf(mx1, __shfl_xor_sync(0xffffffffu, mx1, 2));
        float mn0 = fmaxf(mrow0, mx0), mn1 = fmaxf(mrow1, mx1);
        float sc0 = __expf(mrow0 - mn0), sc1 = __expf(mrow1 - mn1);
        mrow0 = mn0; mrow1 = mn1;

        // ---- exp + pack P fragments + row sum ----
        float sum0 = 0.f, sum1 = 0.f;
        uint32_t pf[8][4];
        #pragma unroll
        for (int kk = 0; kk < 8; kk++) {
            float e00 = __expf(S[2 * kk][0] - mn0),     e01 = __expf(S[2 * kk][1] - mn0);
            float e02 = __expf(S[2 * kk][2] - mn1),     e03 = __expf(S[2 * kk][3] - mn1);
            float e10 = __expf(S[2 * kk + 1][0] - mn0), e11 = __expf(S[2 * kk + 1][1] - mn0);
            float e12 = __expf(S[2 * kk + 1][2] - mn1), e13 = __expf(S[2 * kk + 1][3] - mn1);
            sum0 += e00 + e01 + e10 + e11;
            sum1 += e02 + e03 + e12 + e13;
            pf[kk][0] = pkh2(e00, e01);
            pf[kk][1] = pkh2(e02, e03);
            pf[kk][2] = pkh2(e10, e11);
            pf[kk][3] = pkh2(e12, e13);
        }
        sum0 += __shfl_xor_sync(0xffffffffu, sum0, 1);
        sum0 += __shfl_xor_sync(0xffffffffu, sum0, 2);
        sum1 += __shfl_xor_sync(0xffffffffu, sum1, 1);
        sum1 += __shfl_xor_sync(0xffffffffu, sum1, 2);
        lrow0 = lrow0 * sc0 + sum0;
        lrow1 = lrow1 * sc1 + sum1;
        #pragma unroll
        for (int nt = 0; nt < 16; nt++) {
            O[nt][0] *= sc0; O[nt][1] *= sc0;
            O[nt][2] *= sc1; O[nt][3] *= sc1;
        }

        if (kt < 15) { stage(sK, kt + 1, 1); CP_COMMIT(); CP_WAIT(2); }
        else CP_WAIT(0);
        __syncthreads();

        // ---- PV: O += P · V^T (single pass, V hi only) ----
        uint32_t vb = sb + sV * FSLOT;
        #pragma unroll
        for (int kk = 0; kk < 8; kk++) {
            #pragma unroll
            for (int gg = 0; gg < 8; gg++) {
                uint32_t b0, b1, b2, b3;
                uint32_t r = vb + (gg * 16 + lr) * (LDSTF * 2) + (kk * 16 + lc8) * 2;
                LDSM4(b0, b1, b2, b3, r);
                MMA16816(O[2 * gg],     pf[kk], b0, b2);
                MMA16816(O[2 * gg + 1], pf[kk], b1, b3);
            }
        }
        __syncthreads();
    }

    // ---- epilogue: normalize and write fp16 ----
    float inv0 = 1.f / lrow0, inv1 = 1.f / lrow1;
    f16* ob = aoh + ((size_t)(b * T_ + q0 + wm)) * D_ + h * DK_;
    #pragma unroll
    for (int nt = 0; nt < 16; nt++) {
        int c = nt * 8 + 2 * tg;
        *(__half2*)(ob + (size_t)g * D_ + c) =
            __halves2half2(__float2half_rn(O[nt][0] * inv0), __float2half_rn(O[nt][1] * inv0));
        *(__half2*)(ob + (size_t)(g + 8) * D_ + c) =
            __halves2half2(__float2half_rn(O[nt][2] * inv1), __float2half_rn(O[nt][3] * inv1));
    }
}

// ---------------- output projection ----------------
__global__ void __launch_bounds__(256, 2) mm_out(const f16* aoh,
                                                 const f16* woh, const f16* wol,
                                                 float* __restrict__ out) {
    int m0 = blockIdx.y * 128, n0 = blockIdx.x * 128;
    float acc[2][8][4];
    mm2_body(aoh, D_, m0, BT_, woh, wol, D_, n0, D_, D_, acc);
    ACC_PAIRS(
        *(float2*)&out[(size_t)(m0 + rl) * D_ + n0 + cl] = make_float2(v0, v1);
    );
}

// ---------------- launch ----------------
extern "C" void kernel_launch(void* const* d_in, const int* in_sizes, int n_in,
                              void* d_out, int out_size) {
    (void)in_sizes; (void)n_in; (void)out_size;
    const float* x  = (const float*)d_in[0];
    const float* pe = (const float*)d_in[1];
    const float* Wq = (const float*)d_in[2];
    const float* Wk = (const float*)d_in[3];
    const float* Wv = (const float*)d_in[4];
    const float* Wo = (const float*)d_in[5];
    const float* Wp = (const float*)d_in[6];
    const float* bu = (const float*)d_in[7];
    const float* bv = (const float*)d_in[8];

    f16 *xh, *peh, *wqh, *wql, *wkh, *wkl, *wvh, *wvl, *woh, *wol, *wph, *wpl;
    f16 *quh, *qvh, *kh, *kl, *ph, *pl, *vth, *bdh, *aoh;
    float *v;
    cudaGetSymbolAddress((void**)&xh,  g_xh);
    cudaGetSymbolAddress((void**)&peh, g_peh);
    cudaGetSymbolAddress((void**)&wqh, g_wqh); cudaGetSymbolAddress((void**)&wql, g_wql);
    cudaGetSymbolAddress((void**)&wkh, g_wkh); cudaGetSymbolAddress((void**)&wkl, g_wkl);
    cudaGetSymbolAddress((void**)&wvh, g_wvh); cudaGetSymbolAddress((void**)&wvl, g_wvl);
    cudaGetSymbolAddress((void**)&woh, g_woh); cudaGetSymbolAddress((void**)&wol, g_wol);
    cudaGetSymbolAddress((void**)&wph, g_wph); cudaGetSymbolAddress((void**)&wpl, g_wpl);
    cudaGetSymbolAddress((void**)&quh, g_quh); cudaGetSymbolAddress((void**)&qvh, g_qvh);
    cudaGetSymbolAddress((void**)&kh,  g_kh);  cudaGetSymbolAddress((void**)&kl,  g_kl);
    cudaGetSymbolAddress((void**)&ph,  g_ph);  cudaGetSymbolAddress((void**)&pl,  g_pl);
    cudaGetSymbolAddress((void**)&vth, g_vth);
    cudaGetSymbolAddress((void**)&bdh, g_bdh);
    cudaGetSymbolAddress((void**)&aoh, g_aoh);
    cudaGetSymbolAddress((void**)&v,   g_v);

    cudaFuncSetAttribute(mm_proj,      cudaFuncAttributeMaxDynamicSharedMemorySize, SMEMSZ);
    cudaFuncSetAttribute(scores_bd,    cudaFuncAttributeMaxDynamicSharedMemorySize, SMEMSZ);
    cudaFuncSetAttribute(mm_out,       cudaFuncAttributeMaxDynamicSharedMemorySize, SMEMSZ);
    cudaFuncSetAttribute(flash_kernel, cudaFuncAttributeMaxDynamicSharedMemorySize, FSMEM);

    // fused prologue conversions (x, pe cvt; 5 weight splits)
    prep<<<dim3(BT_ * D_ / 4 / 256, 7), 256>>>(
        x, pe, Wq, Wk, Wv, Wo, Wp, xh, peh,
        wqh, wql, wkh, wkl, wvh, wvl, woh, wol, wph, wpl);

    mm_proj<<<dim3(D_ / 128, BT_ / 128, 4), 256, SMEMSZ>>>(
        xh, peh, wqh, wql, wkh, wkl, wvh, wvl, wph, wpl,
        bu, bv, quh, qvh, kh, kl, v, ph, pl);

    vtrans<<<dim3(T_ / 32, DK_ / 32, B_ * H_), 256>>>(v, vth);

    scores_bd<<<dim3(17, T_ / 128, B_ * H_), 256, SMEMSZ>>>(qvh, ph, pl, bdh);

    flash_kernel<<<dim3(T_ / 128, B_ * H_), 256, FSMEM>>>(quh, kh, kl, vth, bdh, aoh);

    mm_out<<<dim3(D_ / 128, BT_ / 128, 1), 256, SMEMSZ>>>(aoh, woh, wol, (float*)d_out);
}

// round 17
// speedup vs baseline: 1.0671x; 1.0671x over previous
#include <cuda_runtime.h>
#include <cuda_fp16.h>
#include <stdint.h>
#include <math.h>

#define B_  4
#define T_  2048
#define D_  1024
#define H_  8
#define DK_ 128
#define P_  (2*T_-1)
#define BT_ (B_*T_)
#define BDW 2312            // bd band row width (f16 elems)

typedef __half f16;

// ---------------- scratch (device globals: allocation-free) ----------------
static __device__ __align__(16) f16 g_xh [(size_t)BT_ * D_];
static __device__ __align__(16) f16 g_peh[(size_t)P_ * D_];
static __device__ __align__(16) f16 g_wqh[(size_t)D_ * D_], g_wql[(size_t)D_ * D_];
static __device__ __align__(16) f16 g_wkh[(size_t)D_ * D_], g_wkl[(size_t)D_ * D_];
static __device__ __align__(16) f16 g_wvh[(size_t)D_ * D_], g_wvl[(size_t)D_ * D_];
static __device__ __align__(16) f16 g_woh[(size_t)D_ * D_], g_wol[(size_t)D_ * D_];
static __device__ __align__(16) f16 g_wph[(size_t)D_ * D_], g_wpl[(size_t)D_ * D_];
static __device__ __align__(16) f16 g_quh[(size_t)BT_ * D_];
static __device__ __align__(16) f16 g_qvh[(size_t)BT_ * D_];
static __device__ __align__(16) f16 g_kh [(size_t)BT_ * D_], g_kl [(size_t)BT_ * D_];
static __device__ __align__(16) f16 g_ph [(size_t)P_ * D_];
static __device__ __align__(16) float g_v [(size_t)BT_ * D_];
static __device__ __align__(16) f16 g_vth[(size_t)B_ * H_ * DK_ * T_];
static __device__ __align__(16) f16 g_bdh[(size_t)B_ * H_ * T_ * BDW];   // rel-pos band, fp16
static __device__ __align__(16) f16 g_aoh[(size_t)BT_ * D_];

// ============================ helpers ============================
__device__ __forceinline__ uint32_t smem_u32(const void* p) {
    uint32_t a;
    asm("{ .reg .u64 t; cvta.to.shared.u64 t, %1; cvt.u32.u64 %0, t; }" : "=r"(a) : "l"(p));
    return a;
}

__device__ __forceinline__ void split2h(float a, float b, __half2& h, __half2& l) {
    f16 ha = __float2half_rn(a), hb = __float2half_rn(b);
    h = __halves2half2(ha, hb);
    l = __halves2half2(__float2half_rn(a - __half2float(ha)),
                       __float2half_rn(b - __half2float(hb)));
}

__device__ __forceinline__ uint32_t pkh2(float a, float b) {
    __half2 h = __halves2half2(__float2half_rn(a), __float2half_rn(b));
    return *(uint32_t*)&h;
}

#define LDSM4(r0, r1, r2, r3, addr) \
    asm volatile("ldmatrix.sync.aligned.m8n8.x4.shared.b16 {%0,%1,%2,%3}, [%4];" \
        : "=r"(r0), "=r"(r1), "=r"(r2), "=r"(r3) : "r"(addr))

#define MMA16816(c, a, b0, b1) \
    asm volatile("mma.sync.aligned.m16n8k16.row.col.f32.f16.f16.f32 " \
        "{%0,%1,%2,%3}, {%4,%5,%6,%7}, {%8,%9}, {%0,%1,%2,%3};" \
        : "+f"((c)[0]), "+f"((c)[1]), "+f"((c)[2]), "+f"((c)[3]) \
        : "r"((a)[0]), "r"((a)[1]), "r"((a)[2]), "r"((a)[3]), "r"(b0), "r"(b1))

#define CP16(dst, src, sz) \
    asm volatile("cp.async.cg.shared.global [%0], [%1], 16, %2;" \
        :: "r"(dst), "l"(src), "r"(sz))
#define CP_COMMIT() asm volatile("cp.async.commit_group;")
#define CP_WAIT(n)  asm volatile("cp.async.wait_group %0;" :: "n"(n))

// ---------------- fused prologue: y=0 cvt x, y=1 cvt pe, y=2..6 split weights ----------------
__global__ void __launch_bounds__(256) prep(
        const float* __restrict__ x, const float* __restrict__ pe,
        const float* __restrict__ Wq, const float* __restrict__ Wk,
        const float* __restrict__ Wv, const float* __restrict__ Wo,
        const float* __restrict__ Wp,
        f16* __restrict__ xh, f16* __restrict__ peh,
        f16* wqh, f16* wql, f16* wkh, f16* wkl, f16* wvh, f16* wvl,
        f16* woh, f16* wol, f16* wph, f16* wpl) {
    int y = blockIdx.y;
    int i = (blockIdx.x * 256 + threadIdx.x) * 4;
    if (y <= 1) {
        const float* s = (y == 0) ? x : pe;
        f16* h = (y == 0) ? xh : peh;
        int n = (y == 0) ? BT_ * D_ : P_ * D_;
        if (i >= n) return;
        float4 v = *(const float4*)&s[i];
        *(__half2*)&h[i]     = __halves2half2(__float2half_rn(v.x), __float2half_rn(v.y));
        *(__half2*)&h[i + 2] = __halves2half2(__float2half_rn(v.z), __float2half_rn(v.w));
    } else {
        if (i >= D_ * D_) return;
        const float* s = (y == 2) ? Wq : (y == 3) ? Wk : (y == 4) ? Wv : (y == 5) ? Wo : Wp;
        f16* h = (y == 2) ? wqh : (y == 3) ? wkh : (y == 4) ? wvh : (y == 5) ? woh : wph;
        f16* l = (y == 2) ? wql : (y == 3) ? wkl : (y == 4) ? wvl : (y == 5) ? wol : wpl;
        float4 v = *(const float4*)&s[i];
        __half2 h0, l0, h1, l1;
        split2h(v.x, v.y, h0, l0);
        split2h(v.z, v.w, h1, l1);
        *(__half2*)&h[i]     = h0;
        *(__half2*)&h[i + 2] = h1;
        *(__half2*)&l[i]     = l0;
        *(__half2*)&l[i + 2] = l1;
    }
}

// ======== warp-MMA NT GEMM: 128x128 tile, A fp16, B fp16 hi/lo, 2 passes ========
#define KC    32
#define LDST  40
#define ARRB  (128 * LDST * 2)
#define SS    (3 * ARRB)
#define NSTG  3
#define SMEMSZ (NSTG * SS)
#define OFF_AH 0
#define OFF_BH ARRB
#define OFF_BL (2 * ARRB)

__device__ __forceinline__ void mm2_body(
        const f16* __restrict__ Ah, int lda, int m0, int Mrows,
        const f16* __restrict__ Bh, const f16* __restrict__ Bl, int ldb, int n0, int Nrows,
        int K, float acc[2][8][4]) {
    extern __shared__ char dsm[];
    uint32_t sb = smem_u32(dsm);
    int tid = threadIdx.x, lane = tid & 31, wid = tid >> 5;
    int wm = (wid & 3) * 32, wn = (wid >> 2) * 64;
    int lr = lane & 15, lc8 = (lane >> 4) << 3;

    #pragma unroll
    for (int mt = 0; mt < 2; mt++)
        #pragma unroll
        for (int nt = 0; nt < 8; nt++)
            #pragma unroll
            for (int e = 0; e < 4; e++) acc[mt][nt][e] = 0.f;

    auto stage_fill = [&](int st, int kc) {
        uint32_t base = sb + st * SS;
        #pragma unroll
        for (int i = 0; i < 6; i++) {
            int sidx = tid + (i << 8);
            int arr = sidx >> 9;
            int rem = sidx & 511;
            int row = rem >> 2, seg = rem & 3;
            uint32_t doff = arr * ARRB + row * (LDST * 2) + seg * 16;
            const char* src;
            int sz;
            if (arr == 0) {
                int r = m0 + row;
                src = (const char*)(Ah + (size_t)r * lda + kc) + seg * 16;
                sz = (r < Mrows) ? 16 : 0;
            } else if (arr == 1) {
                int r = n0 + row;
                src = (const char*)(Bh + (size_t)r * ldb + kc) + seg * 16;
                sz = (r < Nrows) ? 16 : 0;
            } else {
                int r = n0 + row;
                src = (const char*)(Bl + (size_t)r * ldb + kc) + seg * 16;
                sz = (r < Nrows) ? 16 : 0;
            }
            CP16(base + doff, src, sz);
        }
    };

    const int NC = K / KC;
    stage_fill(0, 0);
    CP_COMMIT();
    if (NC > 1) { stage_fill(1, KC); CP_COMMIT(); }

    for (int c = 0; c < NC; c++) {
        if (c < NC - 1) CP_WAIT(1); else CP_WAIT(0);
        __syncthreads();

        uint32_t abase = sb + (c % NSTG) * SS;
        #pragma unroll
        for (int kk = 0; kk < KC; kk += 16) {
            uint32_t ah[2][4];
            #pragma unroll
            for (int mt = 0; mt < 2; mt++) {
                uint32_t r = abase + OFF_AH + (wm + mt * 16 + lr) * (LDST * 2) + (kk + lc8) * 2;
                LDSM4(ah[mt][0], ah[mt][1], ah[mt][2], ah[mt][3], r);
            }
            #pragma unroll
            for (int g = 0; g < 4; g++) {
                uint32_t bh0, bh1, bh2, bh3, bl0, bl1, bl2, bl3;
                uint32_t r = abase + OFF_BH + (wn + g * 16 + lr) * (LDST * 2) + (kk + lc8) * 2;
                LDSM4(bh0, bh1, bh2, bh3, r);
                r = abase + OFF_BL + (wn + g * 16 + lr) * (LDST * 2) + (kk + lc8) * 2;
                LDSM4(bl0, bl1, bl2, bl3, r);
                #pragma unroll
                for (int mt = 0; mt < 2; mt++) {
                    MMA16816(acc[mt][2 * g],     ah[mt], bh0, bh2);
                    MMA16816(acc[mt][2 * g + 1], ah[mt], bh1, bh3);
                    MMA16816(acc[mt][2 * g],     ah[mt], bl0, bl2);
                    MMA16816(acc[mt][2 * g + 1], ah[mt], bl1, bl3);
                }
            }
        }
        if (c + 2 < NC) { stage_fill((c + 2) % NSTG, (c + 2) * KC); CP_COMMIT(); }
    }
}

#define ACC_PAIRS(...) do {                                                   \
    int lane = threadIdx.x & 31, wid = threadIdx.x >> 5;                      \
    int wm = (wid & 3) * 32, wn = (wid >> 2) * 64;                            \
    int g = lane >> 2, tg = lane & 3;                                         \
    _Pragma("unroll") for (int mt = 0; mt < 2; mt++)                          \
    _Pragma("unroll") for (int hf = 0; hf < 2; hf++) {                        \
        int rl = wm + mt * 16 + g + hf * 8;                                   \
        _Pragma("unroll") for (int nt = 0; nt < 8; nt++) {                    \
            int cl = wn + nt * 8 + tg * 2;                                    \
            float v0 = acc[mt][nt][hf * 2], v1 = acc[mt][nt][hf * 2 + 1];     \
            { __VA_ARGS__ }                                                   \
        }                                                                     \
    }                                                                         \
} while (0)

// ---------------- projections: z=0 q(+biases), 1 k, 2 v, 3 p ----------------
__global__ void __launch_bounds__(256, 2) mm_proj(
        const f16* xh, const f16* peh,
        const f16* wqh, const f16* wql, const f16* wkh, const f16* wkl,
        const f16* wvh, const f16* wvl, const f16* wph, const f16* wpl,
        const float* bu, const float* bv,
        f16* quh, f16* qvh, f16* kh, f16* kl, float* v, f16* ph) {
    int z = blockIdx.z;
    const f16* Ah = (z == 3) ? peh : xh;
    const f16* Bh = (z == 0) ? wqh : (z == 1) ? wkh : (z == 2) ? wvh : wph;
    const f16* Bl = (z == 0) ? wql : (z == 1) ? wkl : (z == 2) ? wvl : wpl;
    int M = (z == 3) ? P_ : BT_;
    int m0 = blockIdx.y * 128;
    if (m0 >= M) return;
    int n0 = blockIdx.x * 128;
    float acc[2][8][4];
    mm2_body(Ah, D_, m0, M, Bh, Bl, D_, n0, D_, D_, acc);

    if (z == 0) {
        ACC_PAIRS(
            int r = m0 + rl, c = n0 + cl;
            size_t idx = (size_t)r * D_ + c;
            *(__half2*)&quh[idx] = __halves2half2(
                __float2half_rn(v0 + __ldg(&bu[c])), __float2half_rn(v1 + __ldg(&bu[c + 1])));
            *(__half2*)&qvh[idx] = __halves2half2(
                __float2half_rn(v0 + __ldg(&bv[c])), __float2half_rn(v1 + __ldg(&bv[c + 1])));
        );
    } else if (z == 1) {
        ACC_PAIRS(
            size_t idx = (size_t)(m0 + rl) * D_ + n0 + cl;
            __half2 h, l;
            split2h(v0, v1, h, l);
            *(__half2*)&kh[idx] = h; *(__half2*)&kl[idx] = l;
        );
    } else if (z == 2) {
        ACC_PAIRS(
            *(float2*)&v[(size_t)(m0 + rl) * D_ + n0 + cl] = make_float2(v0, v1);
        );
    } else {
        ACC_PAIRS(
            int r = m0 + rl;
            if (r < P_) {
                size_t idx = (size_t)r * D_ + n0 + cl;
                *(__half2*)&ph[idx] = __halves2half2(__float2half_rn(v0), __float2half_rn(v1));
            }
        );
    }
}

// ======== scores BD: A-resident streaming diag GEMM (1-pass p) ========
// 512 blocks (16 q-tiles x 32 bh). qv fragments in registers; loop 17 j-tiles.
// Band: bd[q][k + 128], scalar f16 stores, flash reads even-k half2.
#define LDSTB 136
#define BARR  (128 * LDSTB * 2)      // 34816 per slot
#define BSMEM (2 * BARR)             // double-buffered

__global__ void __launch_bounds__(256, 2) scores_bd(const f16* __restrict__ qvh,
                                                    const f16* __restrict__ ph,
                                                    f16* __restrict__ bd) {
    extern __shared__ char dsm[];
    uint32_t sb = smem_u32(dsm);
    int qi = blockIdx.y, bh = blockIdx.z, b = bh >> 3, h = bh & 7;
    int q0 = qi * 128;
    int tid = threadIdx.x, lane = tid & 31, wid = tid >> 5;
    int wm = wid * 16;
    int g = lane >> 2, tg = lane & 3;
    int lr = lane & 15, lc8 = (lane >> 4) << 3;

    // qv fragments resident (K=128 -> 8 kk chunks)
    const f16* qbase = qvh + ((size_t)(b * T_ + q0 + wm)) * D_ + h * DK_;
    uint32_t qvf[8][4];
    #pragma unroll
    for (int kk = 0; kk < 8; kk++) {
        qvf[kk][0] = *(const uint32_t*)(qbase + (size_t)g * D_ + kk * 16 + 2 * tg);
        qvf[kk][1] = *(const uint32_t*)(qbase + (size_t)(g + 8) * D_ + kk * 16 + 2 * tg);
        qvf[kk][2] = *(const uint32_t*)(qbase + (size_t)g * D_ + kk * 16 + 2 * tg + 8);
        qvf[kk][3] = *(const uint32_t*)(qbase + (size_t)(g + 8) * D_ + kk * 16 + 2 * tg + 8);
    }

    const f16* pb = ph + h * DK_;
    auto stage = [&](int slot, int jt) {
        int j0 = (15 - qi + jt) * 128;
        uint32_t base = sb + slot * BARR;
        #pragma unroll
        for (int i = 0; i < 8; i++) {               // 2048 copies: 128 rows x 16 segs x 16B
            int idx = tid + (i << 8);
            int row = idx >> 4, seg = idx & 15;
            int j = j0 + row;
            int sz = (j < P_) ? 16 : 0;
            CP16(base + row * (LDSTB * 2) + seg * 16,
                 (const char*)(pb + (size_t)j * D_) + seg * 16, sz);
        }
    };

    stage(0, 0); CP_COMMIT();

    int q0w = q0 + wm;
    f16* bdo = bd + (size_t)bh * T_ * BDW;

    for (int jt = 0; jt < 17; jt++) {
        if (jt < 16) { stage((jt & 1) ^ 1, jt + 1); CP_COMMIT(); CP_WAIT(1); }
        else CP_WAIT(0);
        __syncthreads();

        float S[16][4];
        #pragma unroll
        for (int nt = 0; nt < 16; nt++)
            #pragma unroll
            for (int e = 0; e < 4; e++) S[nt][e] = 0.f;

        uint32_t base = sb + (jt & 1) * BARR;
        #pragma unroll
        for (int kk = 0; kk < 8; kk++) {
            #pragma unroll
            for (int gg = 0; gg < 8; gg++) {
                uint32_t b0, b1, b2, b3;
                uint32_t r = base + (gg * 16 + lr) * (LDSTB * 2) + (kk * 16 + lc8) * 2;
                LDSM4(b0, b1, b2, b3, r);
                MMA16816(S[2 * gg],     qvf[kk], b0, b2);
                MMA16816(S[2 * gg + 1], qvf[kk], b1, b3);
            }
        }

        // scalar stores: row q -> c = j0 + cl + q - 1919 (= k + 128)
        int j0 = (15 - qi + jt) * 128;
        int cbase = j0 + 2 * tg + (q0w + g) - 1919;
        f16* r0 = &bdo[(size_t)(q0w + g) * BDW];
        f16* r1 = &bdo[(size_t)(q0w + g + 8) * BDW];
        #pragma unroll
        for (int nt = 0; nt < 16; nt++) {
            int c = cbase + nt * 8;
            r0[c]     = __float2half_rn(S[nt][0]);
            r0[c + 1] = __float2half_rn(S[nt][1]);
            r1[c + 8] = __float2half_rn(S[nt][2]);
            r1[c + 9] = __float2half_rn(S[nt][3]);
        }
        __syncthreads();
    }
}

// ---------------- v transpose: vt[bh][dk][t], fp16 ----------------
__global__ void __launch_bounds__(256) vtrans(const float* __restrict__ v,
                                              f16* __restrict__ vth) {
    __shared__ float tile[32][33];
    int bh = blockIdx.z, b = bh >> 3, h = bh & 7;
    int t0 = blockIdx.x * 32, d0 = blockIdx.y * 32;
    int tx = threadIdx.x & 31, ty = threadIdx.x >> 5;
    #pragma unroll
    for (int i = 0; i < 4; ++i) {
        int t = t0 + ty + i * 8;
        tile[ty + i * 8][tx] = v[(size_t)(b * T_ + t) * D_ + h * DK_ + d0 + tx];
    }
    __syncthreads();
    #pragma unroll
    for (int i = 0; i < 4; ++i) {
        int dk = d0 + ty + i * 8;
        vth[((size_t)bh * DK_ + dk) * T_ + t0 + tx] = __float2half_rn(tile[tx][ty + i * 8]);
    }
}

// ======== flash attention: QK(2-pass) + fp16 bd + online softmax + PV(1-pass) ========
#define LDSTF 136
#define FARR  (128 * LDSTF * 2)      // 34816
#define FSLOT (2 * FARR)             // 69632 (hi + lo; V uses hi only)
#define FSMEM (3 * FSLOT)            // 208896

__global__ void __launch_bounds__(256, 1) flash_kernel(
        const f16* __restrict__ quh,
        const f16* __restrict__ kh, const f16* __restrict__ kl,
        const f16* __restrict__ vth,
        const f16* __restrict__ bd, f16* __restrict__ aoh) {
    extern __shared__ char dsm[];
    uint32_t sb = smem_u32(dsm);
    int qt = blockIdx.x, bh = blockIdx.y, b = bh >> 3, h = bh & 7;
    int q0 = qt * 128;
    int tid = threadIdx.x, lane = tid & 31, wid = tid >> 5;
    int wm = wid * 16;
    int g = lane >> 2, tg = lane & 3;
    int lr = lane & 15, lc8 = (lane >> 4) << 3;

    const f16* qbase = quh + ((size_t)(b * T_ + q0 + wm)) * D_ + h * DK_;
    uint32_t quf[8][4];
    #pragma unroll
    for (int kk = 0; kk < 8; kk++) {
        quf[kk][0] = *(const uint32_t*)(qbase + (size_t)g * D_ + kk * 16 + 2 * tg);
        quf[kk][1] = *(const uint32_t*)(qbase + (size_t)(g + 8) * D_ + kk * 16 + 2 * tg);
        quf[kk][2] = *(const uint32_t*)(qbase + (size_t)g * D_ + kk * 16 + 2 * tg + 8);
        quf[kk][3] = *(const uint32_t*)(qbase + (size_t)(g + 8) * D_ + kk * 16 + 2 * tg + 8);
    }

    float O[16][4];
    #pragma unroll
    for (int nt = 0; nt < 16; nt++)
        #pragma unroll
        for (int e = 0; e < 4; e++) O[nt][e] = 0.f;
    float mrow0 = -1e30f, mrow1 = -1e30f, lrow0 = 0.f, lrow1 = 0.f;

    auto stage = [&](int slot, int kt, int kind) {
        uint32_t base = sb + slot * FSLOT;
        if (kind == 0) {
            const f16* sh = kh + ((size_t)(b * T_ + kt * 128)) * D_ + h * DK_;
            const f16* sl = kl + ((size_t)(b * T_ + kt * 128)) * D_ + h * DK_;
            #pragma unroll
            for (int i = 0; i < 8; i++) {
                int idx = tid + (i << 8);
                int row = idx >> 4, seg = idx & 15;
                uint32_t doff = row * (LDSTF * 2) + seg * 16;
                CP16(base + doff,        (const char*)(sh + (size_t)row * D_) + seg * 16, 16);
                CP16(base + FARR + doff, (const char*)(sl + (size_t)row * D_) + seg * 16, 16);
            }
        } else {
            const f16* sh = vth + (size_t)bh * DK_ * T_ + kt * 128;
            #pragma unroll
            for (int i = 0; i < 8; i++) {
                int idx = tid + (i << 8);
                int row = idx >> 4, seg = idx & 15;
                uint32_t doff = row * (LDSTF * 2) + seg * 16;
                CP16(base + doff, (const char*)(sh + (size_t)row * T_) + seg * 16, 16);
            }
        }
    };

    const float scale = 0.08838834764831845f;
    const f16* bdr0 = bd + ((size_t)bh * T_ + q0 + wm + g) * BDW + 2 * tg + 128;
    const f16* bdr1 = bdr0 + (size_t)8 * BDW;

    stage(0, 0, 0); CP_COMMIT();
    stage(1, 0, 1); CP_COMMIT();

    for (int kt = 0; kt < 16; kt++) {
        int sK = (2 * kt) % 3, sV = (2 * kt + 1) % 3;
        if (kt < 15) { stage((2 * kt + 2) % 3, kt + 1, 0); CP_COMMIT(); CP_WAIT(2); }
        else CP_WAIT(1);
        __syncthreads();

        float S[16][4];
        #pragma unroll
        for (int nt = 0; nt < 16; nt++)
            #pragma unroll
            for (int e = 0; e < 4; e++) S[nt][e] = 0.f;
        uint32_t kb = sb + sK * FSLOT;
        #pragma unroll
        for (int kk = 0; kk < 8; kk++) {
            #pragma unroll
            for (int gg = 0; gg < 8; gg++) {
                uint32_t b0, b1, b2, b3, c0, c1, c2, c3;
                uint32_t r = kb + (gg * 16 + lr) * (LDSTF * 2) + (kk * 16 + lc8) * 2;
                LDSM4(b0, b1, b2, b3, r);
                LDSM4(c0, c1, c2, c3, r + FARR);
                MMA16816(S[2 * gg],     quf[kk], b0, b2);
                MMA16816(S[2 * gg + 1], quf[kk], b1, b3);
                MMA16816(S[2 * gg],     quf[kk], c0, c2);
                MMA16816(S[2 * gg + 1], quf[kk], c1, c3);
            }
        }

        float mx0 = -1e30f, mx1 = -1e30f;
        #pragma unroll
        for (int nt = 0; nt < 16; nt++) {
            float2 d0 = __half22float2(*(const __half2*)(bdr0 + kt * 128 + nt * 8));
            float2 d1 = __half22float2(*(const __half2*)(bdr1 + kt * 128 + nt * 8));
            S[nt][0] = (S[nt][0] + d0.x) * scale;
            S[nt][1] = (S[nt][1] + d0.y) * scale;
            S[nt][2] = (S[nt][2] + d1.x) * scale;
            S[nt][3] = (S[nt][3] + d1.y) * scale;
            mx0 = fmaxf(mx0, fmaxf(S[nt][0], S[nt][1]));
            mx1 = fmaxf(mx1, fmaxf(S[nt][2], S[nt][3]));
        }
        mx0 = fmaxf(mx0, __shfl_xor_sync(0xffffffffu, mx0, 1));
        mx0 = fmaxf(mx0, __shfl_xor_sync(0xffffffffu, mx0, 2));
        mx1 = fmaxf(mx1, __shfl_xor_sync(0xffffffffu, mx1, 1));
        mx1 = fmaxf(mx1, __shfl_xor_sync(0xffffffffu, mx1, 2));
        float mn0 = fmaxf(mrow0, mx0), mn1 = fmaxf(mrow1, mx1);
        float sc0 = __expf(mrow0 - mn0), sc1 = __expf(mrow1 - mn1);
        mrow0 = mn0; mrow1 = mn1;

        float sum0 = 0.f, sum1 = 0.f;
        uint32_t pf[8][4];
        #pragma unroll
        for (int kk = 0; kk < 8; kk++) {
            float e00 = __expf(S[2 * kk][0] - mn0),     e01 = __expf(S[2 * kk][1] - mn0);
            float e02 = __expf(S[2 * kk][2] - mn1),     e03 = __expf(S[2 * kk][3] - mn1);
            float e10 = __expf(S[2 * kk + 1][0] - mn0), e11 = __expf(S[2 * kk + 1][1] - mn0);
            float e12 = __expf(S[2 * kk + 1][2] - mn1), e13 = __expf(S[2 * kk + 1][3] - mn1);
            sum0 += e00 + e01 + e10 + e11;
            sum1 += e02 + e03 + e12 + e13;
            pf[kk][0] = pkh2(e00, e01);
            pf[kk][1] = pkh2(e02, e03);
            pf[kk][2] = pkh2(e10, e11);
            pf[kk][3] = pkh2(e12, e13);
        }
        sum0 += __shfl_xor_sync(0xffffffffu, sum0, 1);
        sum0 += __shfl_xor_sync(0xffffffffu, sum0, 2);
        sum1 += __shfl_xor_sync(0xffffffffu, sum1, 1);
        sum1 += __shfl_xor_sync(0xffffffffu, sum1, 2);
        lrow0 = lrow0 * sc0 + sum0;
        lrow1 = lrow1 * sc1 + sum1;
        #pragma unroll
        for (int nt = 0; nt < 16; nt++) {
            O[nt][0] *= sc0; O[nt][1] *= sc0;
            O[nt][2] *= sc1; O[nt][3] *= sc1;
        }

        if (kt < 15) { stage(sK, kt + 1, 1); CP_COMMIT(); CP_WAIT(2); }
        else CP_WAIT(0);
        __syncthreads();

        uint32_t vb = sb + sV * FSLOT;
        #pragma unroll
        for (int kk = 0; kk < 8; kk++) {
            #pragma unroll
            for (int gg = 0; gg < 8; gg++) {
                uint32_t b0, b1, b2, b3;
                uint32_t r = vb + (gg * 16 + lr) * (LDSTF * 2) + (kk * 16 + lc8) * 2;
                LDSM4(b0, b1, b2, b3, r);
                MMA16816(O[2 * gg],     pf[kk], b0, b2);
                MMA16816(O[2 * gg + 1], pf[kk], b1, b3);
            }
        }
        __syncthreads();
    }

    float inv0 = 1.f / lrow0, inv1 = 1.f / lrow1;
    f16* ob = aoh + ((size_t)(b * T_ + q0 + wm)) * D_ + h * DK_;
    #pragma unroll
    for (int nt = 0; nt < 16; nt++) {
        int c = nt * 8 + 2 * tg;
        *(__half2*)(ob + (size_t)g * D_ + c) =
            __halves2half2(__float2half_rn(O[nt][0] * inv0), __float2half_rn(O[nt][1] * inv0));
        *(__half2*)(ob + (size_t)(g + 8) * D_ + c) =
            __halves2half2(__float2half_rn(O[nt][2] * inv1), __float2half_rn(O[nt][3] * inv1));
    }
}

// ---------------- output projection ----------------
__global__ void __launch_bounds__(256, 2) mm_out(const f16* aoh,
                                                 const f16* woh, const f16* wol,
                                                 float* __restrict__ out) {
    int m0 = blockIdx.y * 128, n0 = blockIdx.x * 128;
    float acc[2][8][4];
    mm2_body(aoh, D_, m0, BT_, woh, wol, D_, n0, D_, D_, acc);
    ACC_PAIRS(
        *(float2*)&out[(size_t)(m0 + rl) * D_ + n0 + cl] = make_float2(v0, v1);
    );
}

// ---------------- launch ----------------
extern "C" void kernel_launch(void* const* d_in, const int* in_sizes, int n_in,
                              void* d_out, int out_size) {
    (void)in_sizes; (void)n_in; (void)out_size;
    const float* x  = (const float*)d_in[0];
    const float* pe = (const float*)d_in[1];
    const float* Wq = (const float*)d_in[2];
    const float* Wk = (const float*)d_in[3];
    const float* Wv = (const float*)d_in[4];
    const float* Wo = (const float*)d_in[5];
    const float* Wp = (const float*)d_in[6];
    const float* bu = (const float*)d_in[7];
    const float* bv = (const float*)d_in[8];

    f16 *xh, *peh, *wqh, *wql, *wkh, *wkl, *wvh, *wvl, *woh, *wol, *wph, *wpl;
    f16 *quh, *qvh, *kh, *kl, *ph, *vth, *bdh, *aoh;
    float *v;
    cudaGetSymbolAddress((void**)&xh,  g_xh);
    cudaGetSymbolAddress((void**)&peh, g_peh);
    cudaGetSymbolAddress((void**)&wqh, g_wqh); cudaGetSymbolAddress((void**)&wql, g_wql);
    cudaGetSymbolAddress((void**)&wkh, g_wkh); cudaGetSymbolAddress((void**)&wkl, g_wkl);
    cudaGetSymbolAddress((void**)&wvh, g_wvh); cudaGetSymbolAddress((void**)&wvl, g_wvl);
    cudaGetSymbolAddress((void**)&woh, g_woh); cudaGetSymbolAddress((void**)&wol, g_wol);
    cudaGetSymbolAddress((void**)&wph, g_wph); cudaGetSymbolAddress((void**)&wpl, g_wpl);
    cudaGetSymbolAddress((void**)&quh, g_quh); cudaGetSymbolAddress((void**)&qvh, g_qvh);
    cudaGetSymbolAddress((void**)&kh,  g_kh);  cudaGetSymbolAddress((void**)&kl,  g_kl);
    cudaGetSymbolAddress((void**)&ph,  g_ph);
    cudaGetSymbolAddress((void**)&vth, g_vth);
    cudaGetSymbolAddress((void**)&bdh, g_bdh);
    cudaGetSymbolAddress((void**)&aoh, g_aoh);
    cudaGetSymbolAddress((void**)&v,   g_v);

    cudaFuncSetAttribute(mm_proj,      cudaFuncAttributeMaxDynamicSharedMemorySize, SMEMSZ);
    cudaFuncSetAttribute(scores_bd,    cudaFuncAttributeMaxDynamicSharedMemorySize, BSMEM);
    cudaFuncSetAttribute(mm_out,       cudaFuncAttributeMaxDynamicSharedMemorySize, SMEMSZ);
    cudaFuncSetAttribute(flash_kernel, cudaFuncAttributeMaxDynamicSharedMemorySize, FSMEM);

    prep<<<dim3(BT_ * D_ / 4 / 256, 7), 256>>>(
        x, pe, Wq, Wk, Wv, Wo, Wp, xh, peh,
        wqh, wql, wkh, wkl, wvh, wvl, woh, wol, wph, wpl);

    mm_proj<<<dim3(D_ / 128, BT_ / 128, 4), 256, SMEMSZ>>>(
        xh, peh, wqh, wql, wkh, wkl, wvh, wvl, wph, wpl,
        bu, bv, quh, qvh, kh, kl, v, ph);

    vtrans<<<dim3(T_ / 32, DK_ / 32, B_ * H_), 256>>>(v, vth);

    scores_bd<<<dim3(1, T_ / 128, B_ * H_), 256, BSMEM>>>(qvh, ph, bdh);

    flash_kernel<<<dim3(T_ / 128, B_ * H_), 256, FSMEM>>>(quh, kh, kl, vth, bdh, aoh);

    mm_out<<<dim3(D_ / 128, BT_ / 128, 1), 256, SMEMSZ>>>(aoh, woh, wol, (float*)d_out);
}